// round 1
// baseline (speedup 1.0000x reference)
#include <cuda_runtime.h>

// Problem constants
static constexpr int Bb = 8;
static constexpr int Ss = 2048;
static constexpr int Dd = 1024;
static constexpr int MT = Bb * Ss;           // 16384 total rows
static constexpr float INV_TEMP = 1.0f / 32.0f;

#define BM 128
#define BN 128
#define BK 8
#define TM 8
#define TN 8
#define NTHREADS 256

// Scratch for projected q/k/v (device globals: allocation-free)
__device__ float g_qp[(size_t)MT * Dd];
__device__ float g_kp[(size_t)MT * Dd];
__device__ float g_vp[(size_t)MT * Dd];

// ---------------------------------------------------------------------------
// NT GEMM tile body: C[m,n] = alpha * sum_k A[m,k] * Bt[n,k] (+ bias[n])
// A: [M x K] row-major (lda = K), Bt: [N x K] row-major (ldb = K)
// Tile origin (m0, n0); dims are exact multiples of BM/BN/BK.
// ---------------------------------------------------------------------------
template <bool BIAS>
__device__ __forceinline__ void gemm_nt_tile(
    const float* __restrict__ A, const float* __restrict__ Bt,
    float* __restrict__ C, int K, int ldc,
    const float* __restrict__ bias, float alpha,
    int m0, int n0)
{
    __shared__ __align__(16) float As[BK][BM];
    __shared__ __align__(16) float Bs[BK][BN];

    const int tid = threadIdx.x;
    const int lrow = tid >> 1;          // 0..127
    const int lk   = (tid & 1) * 4;     // 0 or 4
    const int tx = tid & 15;
    const int ty = tid >> 4;

    const float* Ap = A + (size_t)(m0 + lrow) * K + lk;
    const float* Bp = Bt + (size_t)(n0 + lrow) * K + lk;

    float acc[TM][TN];
#pragma unroll
    for (int i = 0; i < TM; i++)
#pragma unroll
        for (int j = 0; j < TN; j++) acc[i][j] = 0.0f;

    for (int kt = 0; kt < K; kt += BK) {
        float4 a4 = *(const float4*)(Ap + kt);
        float4 b4 = *(const float4*)(Bp + kt);
        As[lk + 0][lrow] = a4.x; As[lk + 1][lrow] = a4.y;
        As[lk + 2][lrow] = a4.z; As[lk + 3][lrow] = a4.w;
        Bs[lk + 0][lrow] = b4.x; Bs[lk + 1][lrow] = b4.y;
        Bs[lk + 2][lrow] = b4.z; Bs[lk + 3][lrow] = b4.w;
        __syncthreads();
#pragma unroll
        for (int kk = 0; kk < BK; kk++) {
            float a[TM], b[TN];
            *(float4*)&a[0] = *(const float4*)&As[kk][ty * TM];
            *(float4*)&a[4] = *(const float4*)&As[kk][ty * TM + 4];
            *(float4*)&b[0] = *(const float4*)&Bs[kk][tx * TN];
            *(float4*)&b[4] = *(const float4*)&Bs[kk][tx * TN + 4];
#pragma unroll
            for (int i = 0; i < TM; i++)
#pragma unroll
                for (int j = 0; j < TN; j++)
                    acc[i][j] = fmaf(a[i], b[j], acc[i][j]);
        }
        __syncthreads();
    }

    float bv[TN];
    if (BIAS) {
#pragma unroll
        for (int j = 0; j < TN; j++) bv[j] = bias[n0 + tx * TN + j];
    }
#pragma unroll
    for (int i = 0; i < TM; i++) {
        float* crow = C + (size_t)(m0 + ty * TM + i) * ldc + (n0 + tx * TN);
        float4 r0, r1;
        r0.x = acc[i][0] * alpha; r0.y = acc[i][1] * alpha;
        r0.z = acc[i][2] * alpha; r0.w = acc[i][3] * alpha;
        r1.x = acc[i][4] * alpha; r1.y = acc[i][5] * alpha;
        r1.z = acc[i][6] * alpha; r1.w = acc[i][7] * alpha;
        if (BIAS) {
            r0.x += bv[0]; r0.y += bv[1]; r0.z += bv[2]; r0.w += bv[3];
            r1.x += bv[4]; r1.y += bv[5]; r1.z += bv[6]; r1.w += bv[7];
        }
        ((float4*)crow)[0] = r0;
        ((float4*)crow)[1] = r1;
    }
}

// ---------------------------------------------------------------------------
// Kernel 1: fused QKV projections. z selects which of the three GEMMs.
// qp = q @ Wq^T + bq, etc.  M = 16384, N = K = 1024.
// ---------------------------------------------------------------------------
__global__ __launch_bounds__(NTHREADS) void proj_kernel(
    const float* __restrict__ q, const float* __restrict__ k,
    const float* __restrict__ v,
    const float* __restrict__ Wq, const float* __restrict__ bq,
    const float* __restrict__ Wk, const float* __restrict__ bk,
    const float* __restrict__ Wv, const float* __restrict__ bv)
{
    const int m0 = blockIdx.x * BM;
    const int n0 = blockIdx.y * BN;
    const int z = blockIdx.z;
    const float *X, *W, *bias;
    float* C;
    if (z == 0)      { X = q; W = Wq; bias = bq; C = g_qp; }
    else if (z == 1) { X = k; W = Wk; bias = bk; C = g_kp; }
    else             { X = v; W = Wv; bias = bv; C = g_vp; }
    gemm_nt_tile<true>(X, W, C, Dd, Dd, bias, 1.0f, m0, n0);
}

// ---------------------------------------------------------------------------
// Kernel 2: raw causal scores into attn output buffer.
// attn[b, s, t] = (qp[b,s,:] . kp[b,t,:]) / 32 for tiles touching the lower
// triangle; strictly-upper tiles are skipped (softmax writes 0 there).
// ---------------------------------------------------------------------------
__global__ __launch_bounds__(NTHREADS) void scores_kernel(float* __restrict__ attn)
{
    const int m0 = blockIdx.x * BM;
    const int n0 = blockIdx.y * BN;
    if (n0 > m0 + (BM - 1)) return;   // tile entirely above diagonal
    const int b = blockIdx.z;
    const float* A  = g_qp + (size_t)b * Ss * Dd;
    const float* Bt = g_kp + (size_t)b * Ss * Dd;
    float* C = attn + (size_t)b * Ss * Ss;
    gemm_nt_tile<false>(A, Bt, C, Dd, Ss, nullptr, INV_TEMP, m0, n0);
}

// ---------------------------------------------------------------------------
// Kernel 3: in-place causal row softmax over the attn buffer.
// Row i: valid entries j <= i; j > i set to exactly 0 (matches -1e16 mask).
// One block (256 threads) per row.
// ---------------------------------------------------------------------------
__global__ __launch_bounds__(256) void softmax_kernel(float* __restrict__ attn)
{
    const int r = blockIdx.x;         // 0 .. MT-1
    const int b = r / Ss;
    const int i = r % Ss;
    float* row = attn + (size_t)b * Ss * Ss + (size_t)i * Ss;
    const int tid = threadIdx.x;
    const int valid = i + 1;

    float vals[8];
    int cnt = 0;
    float lmax = -3.0e38f;
    for (int j = tid; j < valid; j += 256) {
        float s = row[j];
        vals[cnt++] = s;
        lmax = fmaxf(lmax, s);
    }

    __shared__ float sred[256];
    sred[tid] = lmax;
    __syncthreads();
    for (int s = 128; s > 0; s >>= 1) {
        if (tid < s) sred[tid] = fmaxf(sred[tid], sred[tid + s]);
        __syncthreads();
    }
    const float mx = sred[0];
    __syncthreads();

    float lsum = 0.0f;
    for (int c = 0; c < cnt; c++) {
        vals[c] = expf(vals[c] - mx);
        lsum += vals[c];
    }
    sred[tid] = lsum;
    __syncthreads();
    for (int s = 128; s > 0; s >>= 1) {
        if (tid < s) sred[tid] += sred[tid + s];
        __syncthreads();
    }
    const float inv = 1.0f / sred[0];

    cnt = 0;
    for (int j = tid; j < valid; j += 256) row[j] = vals[cnt++] * inv;
    for (int j = tid; j < Ss; j += 256)
        if (j >= valid) row[j] = 0.0f;
}

// ---------------------------------------------------------------------------
// Kernel 4: output = attn @ vp (NN GEMM, per batch). attn rows are zero for
// t > i, so the k-loop is truncated at m0 + BM (causal saving).
// ---------------------------------------------------------------------------
__global__ __launch_bounds__(NTHREADS) void av_kernel(
    const float* __restrict__ attn, float* __restrict__ out)
{
    const int m0 = blockIdx.x * BM;
    const int n0 = blockIdx.y * BN;
    const int b = blockIdx.z;
    const float* A  = attn + (size_t)b * Ss * Ss;   // [Ss x Ss]
    const float* Bm = g_vp + (size_t)b * Ss * Dd;   // [Ss x Dd]
    float* C = out + (size_t)b * Ss * Dd;

    __shared__ __align__(16) float As[BK][BM];
    __shared__ __align__(16) float Bs[BK][BN];

    const int tid = threadIdx.x;
    const int lrow = tid >> 1;
    const int lk   = (tid & 1) * 4;
    const int brow = tid >> 5;            // 0..7
    const int bcol = (tid & 31) * 4;      // 0..124
    const int tx = tid & 15;
    const int ty = tid >> 4;

    const float* Ap = A + (size_t)(m0 + lrow) * Ss + lk;
    const float* Bp = Bm + (size_t)brow * Dd + n0 + bcol;

    float acc[TM][TN];
#pragma unroll
    for (int i = 0; i < TM; i++)
#pragma unroll
        for (int j = 0; j < TN; j++) acc[i][j] = 0.0f;

    const int kmax = m0 + BM;  // attn[m, t] == 0 for all t >= m0 + BM
    for (int kt = 0; kt < kmax; kt += BK) {
        float4 a4 = *(const float4*)(Ap + kt);
        float4 b4 = *(const float4*)(Bp + (size_t)kt * Dd);
        As[lk + 0][lrow] = a4.x; As[lk + 1][lrow] = a4.y;
        As[lk + 2][lrow] = a4.z; As[lk + 3][lrow] = a4.w;
        *(float4*)&Bs[brow][bcol] = b4;
        __syncthreads();
#pragma unroll
        for (int kk = 0; kk < BK; kk++) {
            float a[TM], bfr[TN];
            *(float4*)&a[0]   = *(const float4*)&As[kk][ty * TM];
            *(float4*)&a[4]   = *(const float4*)&As[kk][ty * TM + 4];
            *(float4*)&bfr[0] = *(const float4*)&Bs[kk][tx * TN];
            *(float4*)&bfr[4] = *(const float4*)&Bs[kk][tx * TN + 4];
#pragma unroll
            for (int i = 0; i < TM; i++)
#pragma unroll
                for (int j = 0; j < TN; j++)
                    acc[i][j] = fmaf(a[i], bfr[j], acc[i][j]);
        }
        __syncthreads();
    }

#pragma unroll
    for (int i = 0; i < TM; i++) {
        float* crow = C + (size_t)(m0 + ty * TM + i) * Dd + (n0 + tx * TN);
        float4 r0, r1;
        r0.x = acc[i][0]; r0.y = acc[i][1]; r0.z = acc[i][2]; r0.w = acc[i][3];
        r1.x = acc[i][4]; r1.y = acc[i][5]; r1.z = acc[i][6]; r1.w = acc[i][7];
        ((float4*)crow)[0] = r0;
        ((float4*)crow)[1] = r1;
    }
}

// ---------------------------------------------------------------------------
// Host launch. Inputs: q,k,v,Wq,bq,Wk,bk,Wv,bv,mask (mask ignored: causal).
// d_out = [output (B*S*D) | attn (B*S*S)] fp32.
// ---------------------------------------------------------------------------
extern "C" void kernel_launch(void* const* d_in, const int* in_sizes, int n_in,
                              void* d_out, int out_size)
{
    const float* q  = (const float*)d_in[0];
    const float* k  = (const float*)d_in[1];
    const float* v  = (const float*)d_in[2];
    const float* Wq = (const float*)d_in[3];
    const float* bq = (const float*)d_in[4];
    const float* Wk = (const float*)d_in[5];
    const float* bk = (const float*)d_in[6];
    const float* Wv = (const float*)d_in[7];
    const float* bv = (const float*)d_in[8];

    float* out  = (float*)d_out;
    float* outO = out;                                  // [B,S,D]
    float* attn = out + (size_t)Bb * Ss * Dd;           // [B,S,S]

    dim3 blk(NTHREADS);

    // 1) QKV projections
    proj_kernel<<<dim3(MT / BM, Dd / BN, 3), blk>>>(q, k, v, Wq, bq, Wk, bk, Wv, bv);

    // 2) causal raw scores into attn buffer
    scores_kernel<<<dim3(Ss / BM, Ss / BN, Bb), blk>>>(attn);

    // 3) in-place row softmax (+ exact zeros above diagonal)
    softmax_kernel<<<MT, 256>>>(attn);

    // 4) output = attn @ vp
    av_kernel<<<dim3(Ss / BM, Dd / BN, Bb), blk>>>(attn, outO);
}

// round 2
// speedup vs baseline: 5.1021x; 5.1021x over previous
#include <cuda_runtime.h>
#include <cuda_fp16.h>
#include <stdint.h>

// Problem constants
static constexpr int Bb = 8;
static constexpr int Ss = 2048;
static constexpr int Dd = 1024;
static constexpr int MT = Bb * Ss;           // 16384 rows
static constexpr float INV_TEMP = 1.0f / 32.0f;

#define SST 40                   // smem row stride in halfs (32 data + 8 pad)
#define TILE_HALFS (128 * SST)   // one 128x32 tile buffer
#define NTHREADS 256

// fp16 scratch (device globals: allocation-free)
__device__ __half g_qp[(size_t)MT * Dd];
__device__ __half g_kp[(size_t)MT * Dd];
__device__ __half g_vp[(size_t)MT * Dd];
__device__ __half g_vpT[(size_t)MT * Dd];   // [B][D][S]

// ---------------------------------------------------------------------------
// PTX helpers
// ---------------------------------------------------------------------------
__device__ __forceinline__ uint32_t smem_u32(const void* p) {
    return (uint32_t)__cvta_generic_to_shared(p);
}

__device__ __forceinline__ void ldsm4(uint32_t& r0, uint32_t& r1,
                                      uint32_t& r2, uint32_t& r3, uint32_t addr) {
    asm volatile("ldmatrix.sync.aligned.m8n8.x4.shared.b16 {%0,%1,%2,%3}, [%4];"
                 : "=r"(r0), "=r"(r1), "=r"(r2), "=r"(r3) : "r"(addr));
}

__device__ __forceinline__ void mma16816(float c[4], const uint32_t a[4],
                                         const uint32_t b[2]) {
    asm volatile(
        "mma.sync.aligned.m16n8k16.row.col.f32.f16.f16.f32 "
        "{%0,%1,%2,%3}, {%4,%5,%6,%7}, {%8,%9}, {%0,%1,%2,%3};"
        : "+f"(c[0]), "+f"(c[1]), "+f"(c[2]), "+f"(c[3])
        : "r"(a[0]), "r"(a[1]), "r"(a[2]), "r"(a[3]), "r"(b[0]), "r"(b[1]));
}

// ---------------------------------------------------------------------------
// Tile staging: gmem -> regs -> smem(half, SST-stride)
// fp32 source: 128 rows x 32 cols fp32 -> 4 float4 per thread, convert to half
// ---------------------------------------------------------------------------
__device__ __forceinline__ void ld_tile_f32(const float* src, size_t ld, int kt,
                                            float4 r[4], int tid) {
#pragma unroll
    for (int i = 0; i < 4; i++) {
        int lin = i * 256 + tid;
        int row = lin >> 3, c4 = lin & 7;
        r[i] = *(const float4*)(src + (size_t)row * ld + kt + c4 * 4);
    }
}
__device__ __forceinline__ void st_tile_f32(__half* dst, const float4 r[4], int tid) {
#pragma unroll
    for (int i = 0; i < 4; i++) {
        int lin = i * 256 + tid;
        int row = lin >> 3, c4 = lin & 7;
        __half2* p = (__half2*)(dst + row * SST + c4 * 4);
        p[0] = __floats2half2_rn(r[i].x, r[i].y);
        p[1] = __floats2half2_rn(r[i].z, r[i].w);
    }
}
// half source: 128 rows x 32 halfs -> 2 uint4 per thread
__device__ __forceinline__ void ld_tile_h(const __half* src, size_t ld, int kt,
                                          uint4 r[2], int tid) {
#pragma unroll
    for (int i = 0; i < 2; i++) {
        int lin = i * 256 + tid;
        int row = lin >> 2, c8 = lin & 3;
        r[i] = *(const uint4*)(src + (size_t)row * ld + kt + c8 * 8);
    }
}
__device__ __forceinline__ void st_tile_h(__half* dst, const uint4 r[2], int tid) {
#pragma unroll
    for (int i = 0; i < 2; i++) {
        int lin = i * 256 + tid;
        int row = lin >> 2, c8 = lin & 3;
        *(uint4*)(dst + row * SST + c8 * 8) = r[i];
    }
}

// ---------------------------------------------------------------------------
// One 128x128x32 stage of MMA from smem.
// Warp grid 2(m) x 4(n); warp tile 64x32 = 4x4 frags of m16n8k16.
// ---------------------------------------------------------------------------
__device__ __forceinline__ void compute_stage(const __half* As, const __half* Bs,
                                              int wm, int wn, int lane,
                                              float acc[4][4][4]) {
    uint32_t a_base = smem_u32(As) +
        (((wm * 64 + (lane & 15)) * SST + (lane >> 4) * 8)) * 2;
    uint32_t b_base = smem_u32(Bs) +
        (((wn * 32 + (lane >> 4) * 8 + (lane & 7)) * SST + ((lane >> 3) & 1) * 8)) * 2;
#pragma unroll
    for (int ks = 0; ks < 2; ks++) {
        uint32_t af[4][4], bf[4][2];
#pragma unroll
        for (int mi = 0; mi < 4; mi++)
            ldsm4(af[mi][0], af[mi][1], af[mi][2], af[mi][3],
                  a_base + (mi * 16 * SST + ks * 16) * 2);
#pragma unroll
        for (int nj = 0; nj < 2; nj++)
            ldsm4(bf[2 * nj][0], bf[2 * nj][1], bf[2 * nj + 1][0], bf[2 * nj + 1][1],
                  b_base + (nj * 16 * SST + ks * 16) * 2);
#pragma unroll
        for (int mi = 0; mi < 4; mi++)
#pragma unroll
            for (int ni = 0; ni < 4; ni++)
                mma16816(acc[mi][ni], af[mi], bf[ni]);
    }
}

// ---------------------------------------------------------------------------
// Double-buffered GEMM mainloop. A: [..][lda] (row-major, M tile at ptr),
// B: [..][ldb] = Bt[n][k]. K multiple of 32.
// ---------------------------------------------------------------------------
template <bool AF32, bool BF32>
__device__ __forceinline__ void gemm_main(const void* Av, size_t lda,
                                          const void* Bv, size_t ldb, int K,
                                          __half* sm, float acc[4][4][4]) {
    __half* As0 = sm;
    __half* As1 = sm + TILE_HALFS;
    __half* Bs0 = sm + 2 * TILE_HALFS;
    __half* Bs1 = sm + 3 * TILE_HALFS;
    const int tid = threadIdx.x;
    const int lane = tid & 31, warp = tid >> 5;
    const int wm = warp & 1, wn = warp >> 1;

    float4 raf[4], rbf[4];
    uint4 rah[2], rbh[2];

    // prologue: stage 0
    if constexpr (AF32) ld_tile_f32((const float*)Av, lda, 0, raf, tid);
    else                ld_tile_h((const __half*)Av, lda, 0, rah, tid);
    if constexpr (BF32) ld_tile_f32((const float*)Bv, ldb, 0, rbf, tid);
    else                ld_tile_h((const __half*)Bv, ldb, 0, rbh, tid);
    if constexpr (AF32) st_tile_f32(As0, raf, tid); else st_tile_h(As0, rah, tid);
    if constexpr (BF32) st_tile_f32(Bs0, rbf, tid); else st_tile_h(Bs0, rbh, tid);
    __syncthreads();

    const int nst = K / 32;
    for (int s = 0; s < nst; s++) {
        __half* Ac = (s & 1) ? As1 : As0;
        __half* Bc = (s & 1) ? Bs1 : Bs0;
        __half* An = (s & 1) ? As0 : As1;
        __half* Bn = (s & 1) ? Bs0 : Bs1;
        const bool more = (s + 1 < nst);
        if (more) {
            const int kt = (s + 1) * 32;
            if constexpr (AF32) ld_tile_f32((const float*)Av, lda, kt, raf, tid);
            else                ld_tile_h((const __half*)Av, lda, kt, rah, tid);
            if constexpr (BF32) ld_tile_f32((const float*)Bv, ldb, kt, rbf, tid);
            else                ld_tile_h((const __half*)Bv, ldb, kt, rbh, tid);
        }
        compute_stage(Ac, Bc, wm, wn, lane, acc);
        if (more) {
            if constexpr (AF32) st_tile_f32(An, raf, tid); else st_tile_h(An, rah, tid);
            if constexpr (BF32) st_tile_f32(Bn, rbf, tid); else st_tile_h(Bn, rbh, tid);
        }
        __syncthreads();
    }
}

#define ZERO_ACC(acc)                         \
    float acc[4][4][4];                       \
    _Pragma("unroll") for (int i = 0; i < 4; i++) \
    _Pragma("unroll") for (int j = 0; j < 4; j++) \
    _Pragma("unroll") for (int c = 0; c < 4; c++) acc[i][j][c] = 0.0f;

// ---------------------------------------------------------------------------
// Kernel 1: QKV projections (fp32 in, half out). z selects GEMM.
// ---------------------------------------------------------------------------
__global__ __launch_bounds__(NTHREADS) void proj_kernel(
    const float* __restrict__ q, const float* __restrict__ k,
    const float* __restrict__ v,
    const float* __restrict__ Wq, const float* __restrict__ bq,
    const float* __restrict__ Wk, const float* __restrict__ bk,
    const float* __restrict__ Wv, const float* __restrict__ bv) {
    __shared__ __align__(16) __half sm[4 * TILE_HALFS];
    const int m0 = blockIdx.x * 128, n0 = blockIdx.y * 128, z = blockIdx.z;
    const float *X, *W, *bias;
    __half* C;
    if (z == 0)      { X = q; W = Wq; bias = bq; C = g_qp; }
    else if (z == 1) { X = k; W = Wk; bias = bk; C = g_kp; }
    else             { X = v; W = Wv; bias = bv; C = g_vp; }

    ZERO_ACC(acc);
    gemm_main<true, true>(X + (size_t)m0 * Dd, Dd, W + (size_t)n0 * Dd, Dd, Dd, sm, acc);

    const int lane = threadIdx.x & 31, warp = threadIdx.x >> 5;
    const int wm = warp & 1, wn = warp >> 1, g = lane >> 2, tk = lane & 3;
#pragma unroll
    for (int mi = 0; mi < 4; mi++) {
#pragma unroll
        for (int ni = 0; ni < 4; ni++) {
            const int r0 = m0 + wm * 64 + mi * 16 + g;
            const int col = n0 + wn * 32 + ni * 8 + tk * 2;
            const float bx = bias[col], by = bias[col + 1];
            *(__half2*)&C[(size_t)r0 * Dd + col] =
                __floats2half2_rn(acc[mi][ni][0] + bx, acc[mi][ni][1] + by);
            *(__half2*)&C[(size_t)(r0 + 8) * Dd + col] =
                __floats2half2_rn(acc[mi][ni][2] + bx, acc[mi][ni][3] + by);
        }
    }
}

// ---------------------------------------------------------------------------
// Kernel 1b: transpose vp -> vpT ([B][S][D] -> [B][D][S])
// ---------------------------------------------------------------------------
__global__ void transpose_vp_kernel() {
    __shared__ __half s[32][33];
    const int b = blockIdx.z;
    const int t0 = blockIdx.x * 32, d0 = blockIdx.y * 32;
    const __half* src = g_vp + (size_t)b * Ss * Dd;
    __half* dst = g_vpT + (size_t)b * Ss * Dd;
    const int tx = threadIdx.x, ty = threadIdx.y;  // (32, 8)
#pragma unroll
    for (int i = 0; i < 32; i += 8)
        s[ty + i][tx] = src[(size_t)(t0 + ty + i) * Dd + d0 + tx];
    __syncthreads();
#pragma unroll
    for (int i = 0; i < 32; i += 8)
        dst[(size_t)(d0 + ty + i) * Ss + t0 + tx] = s[tx][ty + i];
}

// ---------------------------------------------------------------------------
// Kernel 2: causal raw scores (half in, fp32 logits out, /32)
// ---------------------------------------------------------------------------
__global__ __launch_bounds__(NTHREADS) void scores_kernel(float* __restrict__ attn) {
    const int m0 = blockIdx.x * 128, n0 = blockIdx.y * 128;
    if (n0 > m0 + 127) return;  // entirely above diagonal
    __shared__ __align__(16) __half sm[4 * TILE_HALFS];
    const int b = blockIdx.z;
    const __half* A = g_qp + (size_t)b * Ss * Dd;
    const __half* Bt = g_kp + (size_t)b * Ss * Dd;
    float* C = attn + (size_t)b * Ss * Ss;

    ZERO_ACC(acc);
    gemm_main<false, false>(A + (size_t)m0 * Dd, Dd, Bt + (size_t)n0 * Dd, Dd, Dd, sm, acc);

    const int lane = threadIdx.x & 31, warp = threadIdx.x >> 5;
    const int wm = warp & 1, wn = warp >> 1, g = lane >> 2, tk = lane & 3;
#pragma unroll
    for (int mi = 0; mi < 4; mi++) {
#pragma unroll
        for (int ni = 0; ni < 4; ni++) {
            const int r0 = m0 + wm * 64 + mi * 16 + g;
            const int col = n0 + wn * 32 + ni * 8 + tk * 2;
            float2 lo = make_float2(acc[mi][ni][0] * INV_TEMP, acc[mi][ni][1] * INV_TEMP);
            float2 hi = make_float2(acc[mi][ni][2] * INV_TEMP, acc[mi][ni][3] * INV_TEMP);
            *(float2*)&C[(size_t)r0 * Ss + col] = lo;
            *(float2*)&C[(size_t)(r0 + 8) * Ss + col] = hi;
        }
    }
}

// ---------------------------------------------------------------------------
// Kernel 3: in-place causal row softmax (fp32). Exact zeros above diagonal.
// ---------------------------------------------------------------------------
__global__ __launch_bounds__(256) void softmax_kernel(float* __restrict__ attn) {
    const int r = blockIdx.x;
    const int b = r / Ss;
    const int i = r % Ss;
    float* row = attn + (size_t)b * Ss * Ss + (size_t)i * Ss;
    const int tid = threadIdx.x;
    const int valid = i + 1;

    float vals[8];
    int cnt = 0;
    float lmax = -3.0e38f;
    for (int j = tid; j < valid; j += 256) {
        float s = row[j];
        vals[cnt++] = s;
        lmax = fmaxf(lmax, s);
    }
    __shared__ float sred[256];
    sred[tid] = lmax;
    __syncthreads();
    for (int s = 128; s > 0; s >>= 1) {
        if (tid < s) sred[tid] = fmaxf(sred[tid], sred[tid + s]);
        __syncthreads();
    }
    const float mx = sred[0];
    __syncthreads();

    float lsum = 0.0f;
    for (int c = 0; c < cnt; c++) {
        vals[c] = expf(vals[c] - mx);
        lsum += vals[c];
    }
    sred[tid] = lsum;
    __syncthreads();
    for (int s = 128; s > 0; s >>= 1) {
        if (tid < s) sred[tid] += sred[tid + s];
        __syncthreads();
    }
    const float inv = 1.0f / sred[0];

    cnt = 0;
    for (int j = tid; j < valid; j += 256) row[j] = vals[cnt++] * inv;
    for (int j = tid; j < Ss; j += 256)
        if (j >= valid) row[j] = 0.0f;
}

// ---------------------------------------------------------------------------
// Kernel 4: output = attn @ vp  (attn fp32 -> half on load, vpT half NT GEMM)
// k-loop truncated at m0+128 (causal zeros beyond).
// ---------------------------------------------------------------------------
__global__ __launch_bounds__(NTHREADS) void av_kernel(
    const float* __restrict__ attn, float* __restrict__ out) {
    __shared__ __align__(16) __half sm[4 * TILE_HALFS];
    const int m0 = blockIdx.x * 128, n0 = blockIdx.y * 128;
    const int b = blockIdx.z;
    const float* A = attn + (size_t)b * Ss * Ss;
    const __half* Bt = g_vpT + (size_t)b * Ss * Dd;  // [D][S]
    float* C = out + (size_t)b * Ss * Dd;

    ZERO_ACC(acc);
    const int kmax = m0 + 128;
    gemm_main<true, false>(A + (size_t)m0 * Ss, Ss, Bt + (size_t)n0 * Ss, Ss, kmax, sm, acc);

    const int lane = threadIdx.x & 31, warp = threadIdx.x >> 5;
    const int wm = warp & 1, wn = warp >> 1, g = lane >> 2, tk = lane & 3;
#pragma unroll
    for (int mi = 0; mi < 4; mi++) {
#pragma unroll
        for (int ni = 0; ni < 4; ni++) {
            const int r0 = m0 + wm * 64 + mi * 16 + g;
            const int col = n0 + wn * 32 + ni * 8 + tk * 2;
            *(float2*)&C[(size_t)r0 * Dd + col] =
                make_float2(acc[mi][ni][0], acc[mi][ni][1]);
            *(float2*)&C[(size_t)(r0 + 8) * Dd + col] =
                make_float2(acc[mi][ni][2], acc[mi][ni][3]);
        }
    }
}

// ---------------------------------------------------------------------------
// Host launch. d_out = [output (B*S*D) | attn (B*S*S)] fp32.
// ---------------------------------------------------------------------------
extern "C" void kernel_launch(void* const* d_in, const int* in_sizes, int n_in,
                              void* d_out, int out_size) {
    const float* q  = (const float*)d_in[0];
    const float* k  = (const float*)d_in[1];
    const float* v  = (const float*)d_in[2];
    const float* Wq = (const float*)d_in[3];
    const float* bq = (const float*)d_in[4];
    const float* Wk = (const float*)d_in[5];
    const float* bk = (const float*)d_in[6];
    const float* Wv = (const float*)d_in[7];
    const float* bv = (const float*)d_in[8];

    float* out  = (float*)d_out;
    float* outO = out;                         // [B,S,D]
    float* attn = out + (size_t)Bb * Ss * Dd;  // [B,S,S]

    // 1) QKV projections (fp16 HMMA)
    proj_kernel<<<dim3(MT / 128, Dd / 128, 3), NTHREADS>>>(q, k, v, Wq, bq, Wk, bk, Wv, bv);

    // 1b) vp -> vpT
    transpose_vp_kernel<<<dim3(Ss / 32, Dd / 32, Bb), dim3(32, 8)>>>();

    // 2) causal raw scores
    scores_kernel<<<dim3(Ss / 128, Ss / 128, Bb), NTHREADS>>>(attn);

    // 3) in-place row softmax
    softmax_kernel<<<MT, 256>>>(attn);

    // 4) output = attn @ vp
    av_kernel<<<dim3(Ss / 128, Dd / 128, Bb), NTHREADS>>>(attn, outO);
}